// round 12
// baseline (speedup 1.0000x reference)
#include <cuda_runtime.h>
#include <cuda_bf16.h>
#include <cstdint>

// LinearSpline activation, division-free, channel-folded:
//   t  = x * (s[c]*6.25f)                 (6.25f == float(1/0.16), exact)
//   tc = clamp(t, -25.0f, 24.0f)          (== reference clip-then-divide)
//   ip = (int)floor(tc);  fr = t - ip     (fr from unclamped t, per reference)
//   out = fma(fr, C1-C0, C0)   where (C0,C1) = (c[z+ip]/s, c[z+ip+1]/s)
//
// R12: 256-bit global transactions (Blackwell LDG.E.256 / STG.E.256 via
// ld/st.global.v8.b32). All scheduling axes (ILP, warps, L1, pipelining)
// saturate at ~5.2 TB/s with no SM pipe >43%; the transaction shape is the
// last untested structural knob. 256-bit halves LSU dispatch slots and
// gives the DRAM controller 8KB-contiguous request trains per warp instr.
// Scheduling frozen at the proven point: 3 CTAs x 512 thr (48 warps),
// plain 13KB table (L1 ~185KB), lean in-place chain, ILP2.

#define NUM_ACT 64
#define SIZE    51
#define TABLE   (NUM_ACT * SIZE)   // 3264

__global__ __launch_bounds__(512, 3)
void linear_spline_kernel(const float* __restrict__ x,
                          const float* __restrict__ coef,
                          const float* __restrict__ scale,
                          float*       __restrict__ out,
                          int n8)
{
    __shared__ float sc[TABLE];         // c[i]/s[c], 13.3 KB
    __shared__ float s625[NUM_ACT];     // s[c] * 6.25f

    for (int i = threadIdx.x; i < TABLE; i += 512) {
        int   c  = i / SIZE;
        float rs = 1.0f / scale[c];                      // exact for s==1
        sc[i] = coef[i] * rs;
    }
    if (threadIdx.x < NUM_ACT) {
        s625[threadIdx.x] = scale[threadIdx.x] * 6.25f;  // exact for s==1
    }
    __syncthreads();

    const int stride = gridDim.x * blockDim.x;           // in float8 units
    int i = blockIdx.x * blockDim.x + threadIdx.x;

    // 256-bit load/store: 8 consecutive floats per thread, always within one
    // channel (channel = 16384 floats; i is in float8 units, c = (i>>11)&63).
    #define LD256(r, p)                                                      \
        asm volatile("ld.global.v8.b32 {%0,%1,%2,%3,%4,%5,%6,%7}, [%8];"     \
            : "=r"((r)[0]), "=r"((r)[1]), "=r"((r)[2]), "=r"((r)[3]),        \
              "=r"((r)[4]), "=r"((r)[5]), "=r"((r)[6]), "=r"((r)[7])         \
            : "l"(p))
    #define ST256(p, r)                                                      \
        asm volatile("st.global.v8.b32 [%0], {%1,%2,%3,%4,%5,%6,%7,%8};"     \
            :: "l"(p),                                                       \
               "r"((r)[0]), "r"((r)[1]), "r"((r)[2]), "r"((r)[3]),           \
               "r"((r)[4]), "r"((r)[5]), "r"((r)[6]), "r"((r)[7])            \
            : "memory")

    // ~10 warp-ops + 2 LDS.32 per element; in-place on the packed word.
    #define ELEM(w, zk_, sg_) {                          \
        float v  = __uint_as_float(w);                   \
        float t  = v * (sg_);                            \
        float tc = fminf(fmaxf(t, -25.0f), 24.0f);       \
        int   ip = __float2int_rd(tc);                   \
        float fr = t - (float)ip;                        \
        int p = (zk_) + ip;                              \
        float c0 = sc[p];                                \
        float c1 = sc[p + 1];                            \
        (w) = __float_as_uint(fmaf(fr, c1 - c0, c0)); }

    #define BODY(r, ii) {                                \
        const int c_ = ((ii) >> 11) & (NUM_ACT - 1);     \
        const float sg_ = s625[c_];                      \
        const int zk_ = c_ * SIZE + SIZE / 2;            \
        ELEM((r)[0], zk_, sg_)                           \
        ELEM((r)[1], zk_, sg_)                           \
        ELEM((r)[2], zk_, sg_)                           \
        ELEM((r)[3], zk_, sg_)                           \
        ELEM((r)[4], zk_, sg_)                           \
        ELEM((r)[5], zk_, sg_)                           \
        ELEM((r)[6], zk_, sg_)                           \
        ELEM((r)[7], zk_, sg_) }

    // ILP=2: two independent 256-bit loads (2KB/warp) in flight per trip.
    for (; i + stride < n8; i += 2 * stride) {
        const int j = i + stride;
        uint32_t ra[8], rb[8];
        LD256(ra, x + (size_t)i * 8);
        LD256(rb, x + (size_t)j * 8);

        BODY(ra, i)
        BODY(rb, j)

        ST256(out + (size_t)i * 8, ra);
        ST256(out + (size_t)j * 8, rb);
    }
    // tail
    if (i < n8) {
        uint32_t r[8];
        LD256(r, x + (size_t)i * 8);
        BODY(r, i)
        ST256(out + (size_t)i * 8, r);
    }
    #undef BODY
    #undef ELEM
    #undef ST256
    #undef LD256
}

extern "C" void kernel_launch(void* const* d_in, const int* in_sizes, int n_in,
                              void* d_out, int out_size)
{
    const float* x     = (const float*)d_in[0];
    const float* coef  = (const float*)d_in[1];
    const float* scale = (const float*)d_in[2];
    float* out         = (float*)d_out;

    const int n  = in_sizes[0];   // 33,554,432
    const int n8 = n / 8;         // 4,194,304 (exact)

    const int threads = 512;
    const int blocks  = 148 * 3;  // 3 CTAs/SM = 48 warps, 13KB smem, L1 ~185KB

    linear_spline_kernel<<<blocks, threads>>>(x, coef, scale, out, n8);
}

// round 13
// speedup vs baseline: 1.0728x; 1.0728x over previous
#include <cuda_runtime.h>
#include <cuda_bf16.h>

// LinearSpline activation, division-free, channel-folded:
//   t  = x * (s[c]*6.25f)                 (6.25f == float(1/0.16), exact)
//   tc = clamp(t, -25.0f, 24.0f)          (== reference clip-then-divide)
//   ip = (int)floor(tc);  fr = t - ip     (fr from unclamped t, per reference)
//   out = fma(fr, C1-C0, C0)   where (C0,C1) = (c[z+ip]/s, c[z+ip+1]/s)
//
// R13 = R9 (best bench: 2 CTAs x 768 thr, 48 warps, 13KB table, ILP2)
// + vectorized prologue (float4 table loads, 1 division per channel)
// + __stcs evict-first stores (at matched L1, hints tested mildly positive:
//   R5 50.7% vs R6 52.0% was the wrong-way comparison — DRAM% 50.7 vs 52.0,
//   i.e. noise; mechanism: keep the write stream from displacing read sectors).
// Structure is at the mixed R/W HBM roofline (~5.2TB/s): all SM-side axes
// (ILP, warps, L1, pipelining, 256-bit) measured flat at ncu ~41us.

#define NUM_ACT 64
#define SIZE    51
#define TABLE   (NUM_ACT * SIZE)   // 3264

__global__ __launch_bounds__(768, 2)
void linear_spline_kernel(const float4* __restrict__ x,
                          const float*  __restrict__ coef,
                          const float*  __restrict__ scale,
                          float4*       __restrict__ out,
                          int n4)
{
    __shared__ float sc[TABLE + 1];     // c[i]/s[c], 13.3 KB (+1 pad for v4 fill)
    __shared__ float s625[NUM_ACT];     // s[c] * 6.25f
    __shared__ float srs[NUM_ACT];      // 1/s[c]

    // One division per channel, not per table entry.
    if (threadIdx.x < NUM_ACT) {
        float s = scale[threadIdx.x];
        srs[threadIdx.x]  = 1.0f / s;        // exact for s==1
        s625[threadIdx.x] = s * 6.25f;       // exact for s==1
    }
    __syncthreads();

    // Vectorized table load: 816 float4 = 3264 floats.
    {
        const float4* c4 = (const float4*)coef;
        for (int q = threadIdx.x; q < TABLE / 4; q += 768) {
            float4 v = c4[q];
            int i0 = q * 4;
            sc[i0]     = v.x * srs[(i0)     / SIZE];
            sc[i0 + 1] = v.y * srs[(i0 + 1) / SIZE];
            sc[i0 + 2] = v.z * srs[(i0 + 2) / SIZE];
            sc[i0 + 3] = v.w * srs[(i0 + 3) / SIZE];
        }
    }
    __syncthreads();

    const int stride = gridDim.x * blockDim.x;
    int i = blockIdx.x * blockDim.x + threadIdx.x;

    // ~10 warp-ops + 2 LDS.32 per element; result overwrites the input
    // component to keep the live set at 8 floats. Max idx = 63*51+49+1 = 3263.
    #define ELEM(v, zk_, sg_) {                          \
        float t  = (v) * (sg_);                          \
        float tc = fminf(fmaxf(t, -25.0f), 24.0f);       \
        int   ip = __float2int_rd(tc);                   \
        float fr = t - (float)ip;                        \
        int p = (zk_) + ip;                              \
        float c0 = sc[p];                                \
        float c1 = sc[p + 1];                            \
        (v) = fmaf(fr, c1 - c0, c0); }

    // ILP=2: two independent LDG.128 in flight before any dependent compute.
    for (; i + stride < n4; i += 2 * stride) {
        const int j = i + stride;
        float4 xa = x[i];
        float4 xb = x[j];

        const int ca = (i >> 12) & (NUM_ACT - 1);   // 4096 float4 per channel
        const int cb = (j >> 12) & (NUM_ACT - 1);
        const float sga = s625[ca];
        const float sgb = s625[cb];
        const int zka = ca * SIZE + SIZE / 2;
        const int zkb = cb * SIZE + SIZE / 2;

        ELEM(xa.x, zka, sga)
        ELEM(xa.y, zka, sga)
        ELEM(xa.z, zka, sga)
        ELEM(xa.w, zka, sga)
        ELEM(xb.x, zkb, sgb)
        ELEM(xb.y, zkb, sgb)
        ELEM(xb.z, zkb, sgb)
        ELEM(xb.w, zkb, sgb)

        __stcs(&out[i], xa);    // evict-first: write stream shouldn't displace reads
        __stcs(&out[j], xb);
    }
    // tail
    if (i < n4) {
        float4 xv = x[i];
        const int c = (i >> 12) & (NUM_ACT - 1);
        const float sg = s625[c];
        const int zk = c * SIZE + SIZE / 2;
        ELEM(xv.x, zk, sg)
        ELEM(xv.y, zk, sg)
        ELEM(xv.z, zk, sg)
        ELEM(xv.w, zk, sg)
        __stcs(&out[i], xv);
    }
    #undef ELEM
}

extern "C" void kernel_launch(void* const* d_in, const int* in_sizes, int n_in,
                              void* d_out, int out_size)
{
    const float* x     = (const float*)d_in[0];
    const float* coef  = (const float*)d_in[1];
    const float* scale = (const float*)d_in[2];
    float* out         = (float*)d_out;

    const int n  = in_sizes[0];   // 33,554,432
    const int n4 = n / 4;         // 8,388,608

    const int threads = 768;
    const int blocks  = 148 * 2;  // 2 CTAs/SM = 48 warps, 13KB smem, L1 ~200KB

    linear_spline_kernel<<<blocks, threads>>>(
        (const float4*)x, coef, scale, (float4*)out, n4);
}

// round 14
// speedup vs baseline: 1.1197x; 1.0437x over previous
#include <cuda_runtime.h>
#include <cuda_bf16.h>

// LinearSpline activation, division-free, channel-folded:
//   t  = x * (s[c]*6.25f)                 (6.25f == float(1/0.16), exact)
//   tc = clamp(t, -25.0f, 24.0f)          (== reference clip-then-divide)
//   ip = (int)floor(tc);  fr = t - ip     (fr from unclamped t, per reference)
//   out = fma(fr, C1-C0, C0)   where (C0,C1) = (c[z+ip]/s, c[z+ip+1]/s)
//
// R14 = R13 (best: 2 CTAs x 768, 48 warps, 13KB table, ILP2, __stcs stores,
// vectorized prologue) + __ldlu last-use loads: the x stream is single-touch,
// so evict-first delivery releases L1/L2 sectors and fill slots immediately —
// the exact resource the L1-carveout dose-response proved binding, bought
// without spending carveout. Kernel is at the mixed R/W HBM roofline
// (~5.4TB/s); all structural axes measured flat.

#define NUM_ACT 64
#define SIZE    51
#define TABLE   (NUM_ACT * SIZE)   // 3264

__global__ __launch_bounds__(768, 2)
void linear_spline_kernel(const float4* __restrict__ x,
                          const float*  __restrict__ coef,
                          const float*  __restrict__ scale,
                          float4*       __restrict__ out,
                          int n4)
{
    __shared__ float sc[TABLE + 1];     // c[i]/s[c], 13.3 KB (+1 pad for v4 fill)
    __shared__ float s625[NUM_ACT];     // s[c] * 6.25f
    __shared__ float srs[NUM_ACT];      // 1/s[c]

    // One division per channel, not per table entry.
    if (threadIdx.x < NUM_ACT) {
        float s = scale[threadIdx.x];
        srs[threadIdx.x]  = 1.0f / s;        // exact for s==1
        s625[threadIdx.x] = s * 6.25f;       // exact for s==1
    }
    __syncthreads();

    // Vectorized table load: 816 float4 = 3264 floats.
    {
        const float4* c4 = (const float4*)coef;
        for (int q = threadIdx.x; q < TABLE / 4; q += 768) {
            float4 v = c4[q];
            int i0 = q * 4;
            sc[i0]     = v.x * srs[(i0)     / SIZE];
            sc[i0 + 1] = v.y * srs[(i0 + 1) / SIZE];
            sc[i0 + 2] = v.z * srs[(i0 + 2) / SIZE];
            sc[i0 + 3] = v.w * srs[(i0 + 3) / SIZE];
        }
    }
    __syncthreads();

    const int stride = gridDim.x * blockDim.x;
    int i = blockIdx.x * blockDim.x + threadIdx.x;

    // ~10 warp-ops + 2 LDS.32 per element; result overwrites the input
    // component to keep the live set at 8 floats. Max idx = 63*51+49+1 = 3263.
    #define ELEM(v, zk_, sg_) {                          \
        float t  = (v) * (sg_);                          \
        float tc = fminf(fmaxf(t, -25.0f), 24.0f);       \
        int   ip = __float2int_rd(tc);                   \
        float fr = t - (float)ip;                        \
        int p = (zk_) + ip;                              \
        float c0 = sc[p];                                \
        float c1 = sc[p + 1];                            \
        (v) = fmaf(fr, c1 - c0, c0); }

    // ILP=2: two independent LDG.128 in flight before any dependent compute.
    for (; i + stride < n4; i += 2 * stride) {
        const int j = i + stride;
        float4 xa = __ldlu(&x[i]);   // last-use: evict-first, free fill slots early
        float4 xb = __ldlu(&x[j]);

        const int ca = (i >> 12) & (NUM_ACT - 1);   // 4096 float4 per channel
        const int cb = (j >> 12) & (NUM_ACT - 1);
        const float sga = s625[ca];
        const float sgb = s625[cb];
        const int zka = ca * SIZE + SIZE / 2;
        const int zkb = cb * SIZE + SIZE / 2;

        ELEM(xa.x, zka, sga)
        ELEM(xa.y, zka, sga)
        ELEM(xa.z, zka, sga)
        ELEM(xa.w, zka, sga)
        ELEM(xb.x, zkb, sgb)
        ELEM(xb.y, zkb, sgb)
        ELEM(xb.z, zkb, sgb)
        ELEM(xb.w, zkb, sgb)

        __stcs(&out[i], xa);    // evict-first write stream
        __stcs(&out[j], xb);
    }
    // tail
    if (i < n4) {
        float4 xv = __ldlu(&x[i]);
        const int c = (i >> 12) & (NUM_ACT - 1);
        const float sg = s625[c];
        const int zk = c * SIZE + SIZE / 2;
        ELEM(xv.x, zk, sg)
        ELEM(xv.y, zk, sg)
        ELEM(xv.z, zk, sg)
        ELEM(xv.w, zk, sg)
        __stcs(&out[i], xv);
    }
    #undef ELEM
}

extern "C" void kernel_launch(void* const* d_in, const int* in_sizes, int n_in,
                              void* d_out, int out_size)
{
    const float* x     = (const float*)d_in[0];
    const float* coef  = (const float*)d_in[1];
    const float* scale = (const float*)d_in[2];
    float* out         = (float*)d_out;

    const int n  = in_sizes[0];   // 33,554,432
    const int n4 = n / 4;         // 8,388,608

    const int threads = 768;
    const int blocks  = 148 * 2;  // 2 CTAs/SM = 48 warps, 13KB smem, L1 ~200KB

    linear_spline_kernel<<<blocks, threads>>>(
        (const float4*)x, coef, scale, (float4*)out, n4);
}